// round 1
// baseline (speedup 1.0000x reference)
#include <cuda_runtime.h>
#include <cuda_bf16.h>
#include <math.h>

// Problem constants
#define BSZ   65536
#define FDIM  16
#define CDIM  128
#define HDIM  256
#define LNUM  8
#define KBIN  8
#define TNUM  8
#define PDIM  23      // 3*K-1
#define POUT  184     // T*PDIM
#define KIN1  136     // T + C
#define TBND  3.0f

// Scratch (device globals — no allocations allowed)
__device__ float g_x [BSZ * FDIM];
__device__ float g_h1[BSZ * HDIM];
__device__ float g_h2[BSZ * HDIM];
__device__ float g_p [BSZ * POUT];
__device__ float g_ld[BSZ];

// ---------------------------------------------------------------------------
// GEMM: C[b,n] = act( sum_k A[b,k] * W[k*N+n] + bias[n] )
// GATHER: A row is [x[b, idn(0..7)], context[b, 0..127]]   (Kdim = 136)
// ---------------------------------------------------------------------------
template<bool GATHER, bool RELU>
__global__ void __launch_bounds__(256) gemm_k(
    const float* __restrict__ A,     // x (GATHER) or dense [B,Kdim]
    const float* __restrict__ ctx,   // context (GATHER only)
    const float* __restrict__ W,     // [Kdim, Ndim]
    const float* __restrict__ bias,  // [Ndim]
    float* __restrict__ C,           // [B, Ndim]
    int Kdim, int Ndim, int idoff)
{
    const int BM = 128, BN = 64, BK = 16;
    __shared__ float As[BK][BM + 4];
    __shared__ float Bs[BK][BN];

    const int tid  = threadIdx.x;
    const int brow = blockIdx.y * BM;
    const int bcol = blockIdx.x * BN;
    const int trg  = tid >> 4;   // 0..15 row group (8 rows each)
    const int tcg  = tid & 15;   // 0..15 col group (4 cols each)

    float acc[8][4];
#pragma unroll
    for (int i = 0; i < 8; i++)
#pragma unroll
        for (int j = 0; j < 4; j++) acc[i][j] = 0.f;

    const int nkt = (Kdim + BK - 1) / BK;
    for (int kt = 0; kt < nkt; ++kt) {
        const int k0 = kt * BK;
        // Load A tile: 128x16, 8 elems/thread, transposed into As[k][m]
#pragma unroll
        for (int i = 0; i < 8; i++) {
            int idx = tid + i * 256;
            int m   = idx >> 4;
            int kk  = idx & 15;
            int k   = k0 + kk;
            float v = 0.f;
            if (k < Kdim) {
                int b = brow + m;
                if (GATHER) {
                    v = (k < 8) ? A[b * FDIM + 2 * k + idoff]
                                : ctx[b * CDIM + (k - 8)];
                } else {
                    v = A[b * Kdim + k];
                }
            }
            As[kk][m] = v;
        }
        // Load B tile: 16x64, 4 elems/thread
#pragma unroll
        for (int i = 0; i < 4; i++) {
            int idx = tid + i * 256;
            int kk  = idx >> 6;
            int n   = idx & 63;
            int k   = k0 + kk;
            int nn  = bcol + n;
            Bs[kk][n] = (k < Kdim && nn < Ndim) ? W[k * Ndim + nn] : 0.f;
        }
        __syncthreads();

#pragma unroll
        for (int kk = 0; kk < BK; kk++) {
            float4 b4 = *reinterpret_cast<const float4*>(&Bs[kk][tcg * 4]);
            float bv[4] = { b4.x, b4.y, b4.z, b4.w };
            float av[8];
#pragma unroll
            for (int i = 0; i < 8; i++) av[i] = As[kk][trg * 8 + i];
#pragma unroll
            for (int i = 0; i < 8; i++)
#pragma unroll
                for (int j = 0; j < 4; j++) acc[i][j] += av[i] * bv[j];
        }
        __syncthreads();
    }

    // Epilogue: bias + optional relu
#pragma unroll
    for (int i = 0; i < 8; i++) {
        int b = brow + trg * 8 + i;
#pragma unroll
        for (int j = 0; j < 4; j++) {
            int n = bcol + tcg * 4 + j;
            if (n < Ndim) {
                float v = acc[i][j] + bias[n];
                if (RELU) v = fmaxf(v, 0.f);
                C[b * Ndim + n] = v;
            }
        }
    }
}

// ---------------------------------------------------------------------------
// Spline helpers
// ---------------------------------------------------------------------------
__device__ __forceinline__ float softplusf(float v) {
    return (v > 20.f) ? v : log1pf(expf(v));
}

// softmax over u[8] -> min-width adjusted cumulative knots c[9] in [-TB, TB]
__device__ __forceinline__ void softmax_cum(const float* u, float* c, float minv) {
    float mx = u[0];
#pragma unroll
    for (int j = 1; j < 8; j++) mx = fmaxf(mx, u[j]);
    float e[8], s = 0.f;
#pragma unroll
    for (int j = 0; j < 8; j++) { e[j] = expf(u[j] - mx); s += e[j]; }
    float inv   = 1.f / s;
    float scale = (1.f - minv * 8.f);
    float cum = 0.f;
    c[0] = -TBND;
#pragma unroll
    for (int j = 0; j < 8; j++) {
        cum += minv + scale * e[j] * inv;
        c[j + 1] = 2.f * TBND * cum - TBND;
    }
    c[8] = TBND;
}

// ---------------------------------------------------------------------------
// Spline + reassembly + permutation + logdet accumulation.
// One thread per sample.  troff: parity of transformed features (0 even layer).
// ---------------------------------------------------------------------------
__global__ void __launch_bounds__(256) spline_k(
    const float* __restrict__ p,
    float* __restrict__ xbuf,
    float* __restrict__ ldacc,
    const int* __restrict__ perm,
    int troff, int has_perm)
{
    int b = blockIdx.x * blockDim.x + threadIdx.x;
    if (b >= BSZ) return;

    float xr[FDIM];
#pragma unroll
    for (int j = 0; j < FDIM; j++) xr[j] = xbuf[b * FDIM + j];

    const float* pr = p + (size_t)b * POUT;
    const int idoff = troff ^ 1;

    float xnew[FDIM];
    float ldsum = 0.f;

#pragma unroll 1
    for (int t = 0; t < TNUM; t++) {
        float xt = xr[2 * t + troff];

        float uw[8], uh[8], ud[7];
#pragma unroll
        for (int j = 0; j < 8; j++) uw[j] = pr[t * PDIM + j];
#pragma unroll
        for (int j = 0; j < 8; j++) uh[j] = pr[t * PDIM + 8 + j];
#pragma unroll
        for (int j = 0; j < 7; j++) ud[j] = pr[t * PDIM + 16 + j];

        float cw[9], ch[9], dd[9];
        softmax_cum(uw, cw, 0.001f);
        softmax_cum(uh, ch, 0.001f);
        dd[0] = 1.f; dd[8] = 1.f;   // MIN_D + softplus(log(expm1(1-MIN_D))) == 1.0
#pragma unroll
        for (int j = 1; j < 8; j++) dd[j] = 0.001f + softplusf(ud[j - 1]);

        bool inside = (xt >= -TBND) && (xt <= TBND);
        float xs = fminf(fmaxf(xt, -TBND), TBND);

        int idx = -1;
#pragma unroll
        for (int j = 0; j < 9; j++) idx += (xs >= cw[j]) ? 1 : 0;
        idx = min(max(idx, 0), 7);

        float x0 = cw[idx], bw = cw[idx + 1] - cw[idx];
        float y0 = ch[idx], bh = ch[idx + 1] - ch[idx];
        float delta = bh / bw;
        float d0 = dd[idx], d1 = dd[idx + 1];

        float th   = (xs - x0) / bw;
        float omt  = 1.f - th;
        float th1m = th * omt;
        float num  = bh * (delta * th * th + d0 * th1m);
        float den  = delta + (d0 + d1 - 2.f * delta) * th1m;
        float y    = y0 + num / den;
        float dnum = delta * delta * (d1 * th * th + 2.f * delta * th1m + d0 * omt * omt);
        float ld   = logf(dnum) - 2.f * logf(den);

        xnew[2 * t + troff] = inside ? y : xt;
        xnew[2 * t + idoff] = xr[2 * t + idoff];
        ldsum += inside ? ld : 0.f;
    }

    ldacc[b] += ldsum;

    if (has_perm) {
        int pm[FDIM];
#pragma unroll
        for (int j = 0; j < FDIM; j++) pm[j] = perm[j];
#pragma unroll
        for (int j = 0; j < FDIM; j++) xbuf[b * FDIM + j] = xnew[pm[j]];
    } else {
#pragma unroll
        for (int j = 0; j < FDIM; j++) xbuf[b * FDIM + j] = xnew[j];
    }
}

// ---------------------------------------------------------------------------
__global__ void init_k(const float* __restrict__ inp, float* __restrict__ x,
                       float* __restrict__ ld)
{
    int i = blockIdx.x * blockDim.x + threadIdx.x;
    if (i < BSZ * FDIM) x[i] = fminf(fmaxf(inp[i], -1.f), 1.f);
    if (i < BSZ) ld[i] = 0.f;
}

__global__ void final_k(const float* __restrict__ x, const float* __restrict__ ld,
                        float* __restrict__ out)
{
    int i = blockIdx.x * blockDim.x + threadIdx.x;
    if (i < BSZ * FDIM) {
        out[i] = fminf(fmaxf(x[i], -1.f), 1.f);
    } else if (i < BSZ * FDIM + BSZ) {
        out[i] = ld[i - BSZ * FDIM];
    }
}

// ---------------------------------------------------------------------------
extern "C" void kernel_launch(void* const* d_in, const int* in_sizes, int n_in,
                              void* d_out, int out_size)
{
    const float* inputs  = (const float*)d_in[0];   // [B,16]
    const float* context = (const float*)d_in[1];   // [B,128]
    const float* W1      = (const float*)d_in[2];   // [L,136,256]
    const float* b1      = (const float*)d_in[3];   // [L,256]
    const float* W2      = (const float*)d_in[4];   // [L,256,256]
    const float* b2      = (const float*)d_in[5];   // [L,256]
    const float* W3      = (const float*)d_in[6];   // [L,256,184]
    const float* b3      = (const float*)d_in[7];   // [L,184]
    const int*   perms   = (const int*)  d_in[8];   // [L-1,16]
    float*       out     = (float*)d_out;

    float *xp, *h1p, *h2p, *pp, *ldp;
    cudaGetSymbolAddress((void**)&xp,  g_x);
    cudaGetSymbolAddress((void**)&h1p, g_h1);
    cudaGetSymbolAddress((void**)&h2p, g_h2);
    cudaGetSymbolAddress((void**)&pp,  g_p);
    cudaGetSymbolAddress((void**)&ldp, g_ld);

    init_k<<<(BSZ * FDIM + 255) / 256, 256>>>(inputs, xp, ldp);

    for (int i = 0; i < LNUM; i++) {
        // layer even: tr = even indices (troff=0), idn = odd (idoff=1)
        const int troff = (i % 2 == 0) ? 0 : 1;
        const int idoff = troff ^ 1;

        gemm_k<true, true><<<dim3(HDIM / 64, BSZ / 128), 256>>>(
            xp, context, W1 + (size_t)i * KIN1 * HDIM, b1 + (size_t)i * HDIM,
            h1p, KIN1, HDIM, idoff);

        gemm_k<false, true><<<dim3(HDIM / 64, BSZ / 128), 256>>>(
            h1p, nullptr, W2 + (size_t)i * HDIM * HDIM, b2 + (size_t)i * HDIM,
            h2p, HDIM, HDIM, 0);

        gemm_k<false, false><<<dim3((POUT + 63) / 64, BSZ / 128), 256>>>(
            h2p, nullptr, W3 + (size_t)i * HDIM * POUT, b3 + (size_t)i * POUT,
            pp, HDIM, POUT, 0);

        spline_k<<<BSZ / 256, 256>>>(pp, xp, ldp,
                                     perms + (size_t)i * FDIM, troff,
                                     (i < LNUM - 1) ? 1 : 0);
    }

    final_k<<<(BSZ * FDIM + BSZ + 255) / 256, 256>>>(xp, ldp, out);
}

// round 12
// speedup vs baseline: 1.9399x; 1.9399x over previous
#include <cuda_runtime.h>
#include <cuda_bf16.h>
#include <math.h>
#include <stdint.h>

// ---------------------------------------------------------------------------
// Problem constants
// ---------------------------------------------------------------------------
#define BSZ   65536
#define FDIM  16
#define CDIM  128
#define HDIM  256
#define LNUM  8
#define TNUM  8
#define PDIM  23
#define POUT  184
#define TBND  3.0f

#define KP1   192     // padded K for layer-1 GEMM (real K=136)
#define KP2   256
#define NP3   192     // padded N for W3 (real 184)

// ---------------------------------------------------------------------------
// Device-global scratch
// ---------------------------------------------------------------------------
__device__ float g_x [BSZ * FDIM];
__device__ float g_h1[(size_t)BSZ * HDIM];
__device__ float g_h2[(size_t)BSZ * HDIM];
__device__ float g_p [(size_t)BSZ * POUT];
__device__ float g_ld[BSZ];
__device__ __align__(16) __nv_bfloat16 g_w1h[LNUM * HDIM * KP1], g_w1l[LNUM * HDIM * KP1];
__device__ __align__(16) __nv_bfloat16 g_w2h[LNUM * HDIM * KP2], g_w2l[LNUM * HDIM * KP2];
__device__ __align__(16) __nv_bfloat16 g_w3h[LNUM * NP3  * KP2], g_w3l[LNUM * NP3  * KP2];

// ---------------------------------------------------------------------------
// Helpers (baseline PTX only — no tcgen05/'a'-target features)
// ---------------------------------------------------------------------------
__device__ __forceinline__ uint32_t smem_u32(const void* p) {
    uint32_t a;
    asm("{ .reg .u64 t; cvta.to.shared.u64 t, %1; cvt.u32.u64 %0, t; }"
        : "=r"(a) : "l"(p));
    return a;
}
__device__ __forceinline__ void ldmx4(uint32_t* r, uint32_t addr) {
    asm volatile("ldmatrix.sync.aligned.m8n8.x4.shared.b16 {%0,%1,%2,%3}, [%4];"
                 : "=r"(r[0]), "=r"(r[1]), "=r"(r[2]), "=r"(r[3]) : "r"(addr));
}
__device__ __forceinline__ void mma16816(float* c, const uint32_t* a, const uint32_t* b) {
    asm volatile(
        "mma.sync.aligned.m16n8k16.row.col.f32.bf16.bf16.f32 "
        "{%0,%1,%2,%3}, {%4,%5,%6,%7}, {%8,%9}, {%0,%1,%2,%3};"
        : "+f"(c[0]), "+f"(c[1]), "+f"(c[2]), "+f"(c[3])
        : "r"(a[0]), "r"(a[1]), "r"(a[2]), "r"(a[3]), "r"(b[0]), "r"(b[1]));
}
__device__ __forceinline__ uint32_t pack_bf(__nv_bfloat16 a, __nv_bfloat16 b) {
    return (uint32_t)__bfloat16_as_ushort(a) | ((uint32_t)__bfloat16_as_ushort(b) << 16);
}

#define SW128(off) ((off) ^ (((off) >> 3) & 0x70))

// SMEM layout (single buffer): AHI 16K | ALO 16K | BHI 8K | BLO 8K = 48K
#define ALO_OFF 16384
#define BHI_OFF 32768
#define BLO_OFF 40960
#define SMEM_DYN 49152

// ---------------------------------------------------------------------------
// mma.sync GEMM: Of[128 x NT] = act( A[128 x KA] * W^T + bias )
//   A fp32 (or GATHER from x+ctx), converted to bf16 hi/lo on the fly.
//   W pre-transposed [Npad, KA] and pre-split hi/lo bf16.
//   3-term split accumulation into fp32: AhBh + AhBl + AlBh.
// ---------------------------------------------------------------------------
template<int NC, int NT, int KA, bool GATHER, bool RELU>
__global__ void __launch_bounds__(256, 2) gemm_mma(
    const float* __restrict__ Af, const float* __restrict__ ctx,
    const __nv_bfloat16* __restrict__ Bh, const __nv_bfloat16* __restrict__ Bl,
    const float* __restrict__ bias, float* __restrict__ Of, int idoff)
{
    extern __shared__ __align__(128) char smem[];
    const uint32_t sb = smem_u32(smem);
    const int tid = threadIdx.x, lane = tid & 31, wid = tid >> 5;
    const int wm = wid & 3, wn = wid >> 2;
    const int brow = blockIdx.y * 128, bcol = blockIdx.x * 64;

    float acc[2][4][4];
#pragma unroll
    for (int i = 0; i < 2; i++)
#pragma unroll
        for (int j = 0; j < 4; j++)
#pragma unroll
            for (int q = 0; q < 4; q++) acc[i][j][q] = 0.f;

    for (int c = 0; c < NC; ++c) {
        const int k0 = c * 64;
        // ---- stage A tile (128 x 64) as bf16 hi/lo, SW128 ----
        if (GATHER) {
#pragma unroll
            for (int t = 0; t < 16; t++) {
                int i = tid + t * 256;
                int row = i >> 5, p = i & 31;
                int b = brow + row;
                int k = k0 + 2 * p;
                float v0 = 0.f, v1 = 0.f;
                if (k < 8)        v0 = Af[b * FDIM + 2 * k + idoff];
                else if (k < 136) v0 = ctx[b * CDIM + k - 8];
                int k2 = k + 1;
                if (k2 < 8)        v1 = Af[b * FDIM + 2 * k2 + idoff];
                else if (k2 < 136) v1 = ctx[b * CDIM + k2 - 8];
                __nv_bfloat16 h0 = __float2bfloat16(v0), h1 = __float2bfloat16(v1);
                __nv_bfloat16 l0 = __float2bfloat16(v0 - __bfloat162float(h0));
                __nv_bfloat16 l1 = __float2bfloat16(v1 - __bfloat162float(h1));
                uint32_t off = SW128((uint32_t)(row * 128 + p * 4));
                *(uint32_t*)(smem + off)           = pack_bf(h0, h1);
                *(uint32_t*)(smem + ALO_OFF + off) = pack_bf(l0, l1);
            }
        } else {
#pragma unroll
            for (int t = 0; t < 8; t++) {
                int i = tid + t * 256;
                int row = i >> 4, seg = i & 15;
                const float4 v = *(const float4*)(Af + (size_t)(brow + row) * KA + k0 + seg * 4);
                __nv_bfloat16 h0 = __float2bfloat16(v.x), h1 = __float2bfloat16(v.y);
                __nv_bfloat16 h2 = __float2bfloat16(v.z), h3 = __float2bfloat16(v.w);
                __nv_bfloat16 l0 = __float2bfloat16(v.x - __bfloat162float(h0));
                __nv_bfloat16 l1 = __float2bfloat16(v.y - __bfloat162float(h1));
                __nv_bfloat16 l2 = __float2bfloat16(v.z - __bfloat162float(h2));
                __nv_bfloat16 l3 = __float2bfloat16(v.w - __bfloat162float(h3));
                uint32_t off = SW128((uint32_t)(row * 128 + seg * 8));
                *(uint2*)(smem + off)           = make_uint2(pack_bf(h0, h1), pack_bf(h2, h3));
                *(uint2*)(smem + ALO_OFF + off) = make_uint2(pack_bf(l0, l1), pack_bf(l2, l3));
            }
        }
        // ---- stage B tile (64 x 64) hi/lo, SW128 ----
#pragma unroll
        for (int t = 0; t < 2; t++) {
            int i = tid + t * 256;
            int row = i >> 3, seg = i & 7;
            size_t src = (size_t)(bcol + row) * KA + k0 + seg * 8;
            uint32_t off = SW128((uint32_t)(row * 128 + seg * 16));
            *(uint4*)(smem + BHI_OFF + off) = *(const uint4*)(Bh + src);
            *(uint4*)(smem + BLO_OFF + off) = *(const uint4*)(Bl + src);
        }
        __syncthreads();

        // ---- compute: 4 k16 steps ----
#pragma unroll
        for (int ks = 0; ks < 4; ks++) {
            uint32_t ah[8], al[8], bh[8], bl[8];
#pragma unroll
            for (int mf = 0; mf < 2; mf++) {
                int arow = wm * 32 + mf * 16 + (lane & 15);
                int kb   = ks * 32 + ((lane >> 4) << 4);
                uint32_t off = SW128((uint32_t)(arow * 128 + kb));
                ldmx4(&ah[mf * 4], sb + off);
                ldmx4(&al[mf * 4], sb + ALO_OFF + off);
            }
#pragma unroll
            for (int g = 0; g < 2; g++) {
                int nrow = wn * 32 + g * 16 + ((lane >> 4) << 3) + (lane & 7);
                int kb   = ks * 32 + (((lane >> 3) & 1) << 4);
                uint32_t off = SW128((uint32_t)(nrow * 128 + kb));
                ldmx4(&bh[g * 4], sb + BHI_OFF + off);
                ldmx4(&bl[g * 4], sb + BLO_OFF + off);
            }
#pragma unroll
            for (int mf = 0; mf < 2; mf++)
#pragma unroll
                for (int nf = 0; nf < 4; nf++) {
                    const int bi = (nf >> 1) * 4 + (nf & 1) * 2;
                    mma16816(acc[mf][nf], &ah[mf * 4], &bh[bi]);
                    mma16816(acc[mf][nf], &ah[mf * 4], &bl[bi]);
                    mma16816(acc[mf][nf], &al[mf * 4], &bh[bi]);
                }
        }
        __syncthreads();
    }

    // ---- epilogue: bias + optional relu, fp32 out ----
#pragma unroll
    for (int mf = 0; mf < 2; mf++) {
        int r0 = brow + wm * 32 + mf * 16 + (lane >> 2);
#pragma unroll
        for (int nf = 0; nf < 4; nf++) {
            int col = bcol + wn * 32 + nf * 8 + 2 * (lane & 3);
            if (col < NT) {
                float b0 = bias[col], b1 = bias[col + 1];
                float v0 = acc[mf][nf][0] + b0, v1 = acc[mf][nf][1] + b1;
                float v2 = acc[mf][nf][2] + b0, v3 = acc[mf][nf][3] + b1;
                if (RELU) {
                    v0 = fmaxf(v0, 0.f); v1 = fmaxf(v1, 0.f);
                    v2 = fmaxf(v2, 0.f); v3 = fmaxf(v3, 0.f);
                }
                float2* d0 = (float2*)(Of + (size_t)r0 * NT + col);
                float2* d1 = (float2*)(Of + (size_t)(r0 + 8) * NT + col);
                *d0 = make_float2(v0, v1);
                *d1 = make_float2(v2, v3);
            }
        }
    }
}

// ---------------------------------------------------------------------------
// Weight prep: [L,KREAL,NREAL] -> transposed [L,NN,KP] bf16 hi/lo (zero pad).
// ---------------------------------------------------------------------------
template<int KREAL, int NREAL, int NN, int KP>
__global__ void prep_k(const float* __restrict__ W,
                       __nv_bfloat16* __restrict__ Bh,
                       __nv_bfloat16* __restrict__ Bl)
{
    const size_t total = (size_t)LNUM * NN * KP;
    size_t idx = (size_t)blockIdx.x * blockDim.x + threadIdx.x;
    if (idx >= total) return;
    const int k = (int)(idx % KP);
    const int n = (int)((idx / KP) % NN);
    const int l = (int)(idx / ((size_t)NN * KP));
    float v = (k < KREAL && n < NREAL)
                ? W[((size_t)l * KREAL + k) * NREAL + n] : 0.f;
    __nv_bfloat16 h = __float2bfloat16(v);
    Bh[idx] = h;
    Bl[idx] = __float2bfloat16(v - __bfloat162float(h));
}

// ---------------------------------------------------------------------------
// Spline kernel (validated in R1)
// ---------------------------------------------------------------------------
__device__ __forceinline__ float softplusf(float v) {
    return (v > 20.f) ? v : log1pf(expf(v));
}
__device__ __forceinline__ void softmax_cum(const float* u, float* c, float minv) {
    float mx = u[0];
#pragma unroll
    for (int j = 1; j < 8; j++) mx = fmaxf(mx, u[j]);
    float e[8], s = 0.f;
#pragma unroll
    for (int j = 0; j < 8; j++) { e[j] = expf(u[j] - mx); s += e[j]; }
    float inv = 1.f / s;
    float scale = (1.f - minv * 8.f);
    float cum = 0.f;
    c[0] = -TBND;
#pragma unroll
    for (int j = 0; j < 8; j++) {
        cum += minv + scale * e[j] * inv;
        c[j + 1] = 2.f * TBND * cum - TBND;
    }
    c[8] = TBND;
}

__global__ void __launch_bounds__(256) spline_k(
    const float* __restrict__ p,
    float* __restrict__ xbuf,
    float* __restrict__ ldacc,
    const int* __restrict__ perm,
    int troff, int has_perm)
{
    int b = blockIdx.x * blockDim.x + threadIdx.x;
    if (b >= BSZ) return;

    float xr[FDIM];
#pragma unroll
    for (int j = 0; j < FDIM; j++) xr[j] = xbuf[b * FDIM + j];

    const float* pr = p + (size_t)b * POUT;
    const int idoff = troff ^ 1;

    float xnew[FDIM];
    float ldsum = 0.f;

#pragma unroll 1
    for (int t = 0; t < TNUM; t++) {
        float xt = xr[2 * t + troff];

        float uw[8], uh[8], ud[7];
#pragma unroll
        for (int j = 0; j < 8; j++) uw[j] = pr[t * PDIM + j];
#pragma unroll
        for (int j = 0; j < 8; j++) uh[j] = pr[t * PDIM + 8 + j];
#pragma unroll
        for (int j = 0; j < 7; j++) ud[j] = pr[t * PDIM + 16 + j];

        float cw[9], ch[9], dd[9];
        softmax_cum(uw, cw, 0.001f);
        softmax_cum(uh, ch, 0.001f);
        dd[0] = 1.f; dd[8] = 1.f;
#pragma unroll
        for (int j = 1; j < 8; j++) dd[j] = 0.001f + softplusf(ud[j - 1]);

        bool inside = (xt >= -TBND) && (xt <= TBND);
        float xs = fminf(fmaxf(xt, -TBND), TBND);

        int idx = -1;
#pragma unroll
        for (int j = 0; j < 9; j++) idx += (xs >= cw[j]) ? 1 : 0;
        idx = min(max(idx, 0), 7);

        float x0 = cw[idx], bw = cw[idx + 1] - cw[idx];
        float y0 = ch[idx], bh = ch[idx + 1] - ch[idx];
        float delta = bh / bw;
        float d0 = dd[idx], d1 = dd[idx + 1];

        float th   = (xs - x0) / bw;
        float omt  = 1.f - th;
        float th1m = th * omt;
        float num  = bh * (delta * th * th + d0 * th1m);
        float den  = delta + (d0 + d1 - 2.f * delta) * th1m;
        float y    = y0 + num / den;
        float dnum = delta * delta * (d1 * th * th + 2.f * delta * th1m + d0 * omt * omt);
        float ld   = logf(dnum) - 2.f * logf(den);

        xnew[2 * t + troff] = inside ? y : xt;
        xnew[2 * t + idoff] = xr[2 * t + idoff];
        ldsum += inside ? ld : 0.f;
    }

    ldacc[b] += ldsum;

    if (has_perm) {
        int pm[FDIM];
#pragma unroll
        for (int j = 0; j < FDIM; j++) pm[j] = perm[j];
#pragma unroll
        for (int j = 0; j < FDIM; j++) xbuf[b * FDIM + j] = xnew[pm[j]];
    } else {
#pragma unroll
        for (int j = 0; j < FDIM; j++) xbuf[b * FDIM + j] = xnew[j];
    }
}

// ---------------------------------------------------------------------------
__global__ void init_k(const float* __restrict__ inp, float* __restrict__ x,
                       float* __restrict__ ld)
{
    int i = blockIdx.x * blockDim.x + threadIdx.x;
    if (i < BSZ * FDIM) x[i] = fminf(fmaxf(inp[i], -1.f), 1.f);
    if (i < BSZ) ld[i] = 0.f;
}

__global__ void final_k(const float* __restrict__ x, const float* __restrict__ ld,
                        float* __restrict__ out)
{
    int i = blockIdx.x * blockDim.x + threadIdx.x;
    if (i < BSZ * FDIM) {
        out[i] = fminf(fmaxf(x[i], -1.f), 1.f);
    } else if (i < BSZ * FDIM + BSZ) {
        out[i] = ld[i - BSZ * FDIM];
    }
}

// ---------------------------------------------------------------------------
extern "C" void kernel_launch(void* const* d_in, const int* in_sizes, int n_in,
                              void* d_out, int out_size)
{
    const float* inputs  = (const float*)d_in[0];
    const float* context = (const float*)d_in[1];
    const float* W1      = (const float*)d_in[2];
    const float* b1      = (const float*)d_in[3];
    const float* W2      = (const float*)d_in[4];
    const float* b2      = (const float*)d_in[5];
    const float* W3      = (const float*)d_in[6];
    const float* b3      = (const float*)d_in[7];
    const int*   perms   = (const int*)  d_in[8];
    float*       out     = (float*)d_out;

    float *xp, *h1p, *h2p, *pp, *ldp;
    __nv_bfloat16 *w1h, *w1l, *w2h, *w2l, *w3h, *w3l;
    cudaGetSymbolAddress((void**)&xp,  g_x);
    cudaGetSymbolAddress((void**)&h1p, g_h1);
    cudaGetSymbolAddress((void**)&h2p, g_h2);
    cudaGetSymbolAddress((void**)&pp,  g_p);
    cudaGetSymbolAddress((void**)&ldp, g_ld);
    cudaGetSymbolAddress((void**)&w1h, g_w1h);
    cudaGetSymbolAddress((void**)&w1l, g_w1l);
    cudaGetSymbolAddress((void**)&w2h, g_w2h);
    cudaGetSymbolAddress((void**)&w2l, g_w2l);
    cudaGetSymbolAddress((void**)&w3h, g_w3h);
    cudaGetSymbolAddress((void**)&w3l, g_w3l);

    auto g1 = gemm_mma<3, HDIM, KP1, true,  true >;
    auto g2 = gemm_mma<4, HDIM, KP2, false, true >;
    auto g3 = gemm_mma<4, POUT, KP2, false, false>;
    cudaFuncSetAttribute(g1, cudaFuncAttributeMaxDynamicSharedMemorySize, SMEM_DYN);
    cudaFuncSetAttribute(g2, cudaFuncAttributeMaxDynamicSharedMemorySize, SMEM_DYN);
    cudaFuncSetAttribute(g3, cudaFuncAttributeMaxDynamicSharedMemorySize, SMEM_DYN);

    // weight prep (transpose + split + pad)
    {
        size_t t1 = (size_t)LNUM * HDIM * KP1;
        size_t t2 = (size_t)LNUM * HDIM * KP2;
        size_t t3 = (size_t)LNUM * NP3  * KP2;
        prep_k<136, 256, 256, KP1><<<(unsigned)((t1 + 255) / 256), 256>>>(W1, w1h, w1l);
        prep_k<256, 256, 256, KP2><<<(unsigned)((t2 + 255) / 256), 256>>>(W2, w2h, w2l);
        prep_k<256, 184, NP3, KP2><<<(unsigned)((t3 + 255) / 256), 256>>>(W3, w3h, w3l);
    }

    init_k<<<(BSZ * FDIM + 255) / 256, 256>>>(inputs, xp, ldp);

    for (int i = 0; i < LNUM; i++) {
        const int troff = (i % 2 == 0) ? 0 : 1;
        const int idoff = troff ^ 1;

        g1<<<dim3(HDIM / 64, BSZ / 128), 256, SMEM_DYN>>>(
            xp, context,
            w1h + (size_t)i * HDIM * KP1, w1l + (size_t)i * HDIM * KP1,
            b1 + (size_t)i * HDIM, h1p, idoff);

        g2<<<dim3(HDIM / 64, BSZ / 128), 256, SMEM_DYN>>>(
            h1p, nullptr,
            w2h + (size_t)i * HDIM * KP2, w2l + (size_t)i * HDIM * KP2,
            b2 + (size_t)i * HDIM, h2p, 0);

        g3<<<dim3(NP3 / 64, BSZ / 128), 256, SMEM_DYN>>>(
            h2p, nullptr,
            w3h + (size_t)i * NP3 * KP2, w3l + (size_t)i * NP3 * KP2,
            b3 + (size_t)i * POUT, pp, 0);

        spline_k<<<BSZ / 256, 256>>>(pp, xp, ldp,
                                     perms + (size_t)i * FDIM, troff,
                                     (i < LNUM - 1) ? 1 : 0);
    }

    final_k<<<(BSZ * FDIM + BSZ + 255) / 256, 256>>>(xp, ldp, out);
}